// round 14
// baseline (speedup 1.0000x reference)
#include <cuda_runtime.h>

// Problem constants (fixed shapes for this problem)
#define CCH  256      // channels
#define KCB  8192     // codebook size
#define NMAX 32768    // tokens

// ---------------- scratch (device globals; no allocations allowed) ----------
__device__ float              g_codebook[KCB * CCH];   // 8 MB
__device__ float              g_cbsq[KCB];
__device__ unsigned long long g_best[NMAX];            // packed (score_key<<32 | k)
__device__ float              g_loss_sum;

// ---------------- helpers ---------------------------------------------------
// order-preserving float -> uint mapping (no NaNs expected)
__device__ __forceinline__ unsigned long long pack_key(float s, int k) {
    unsigned u = __float_as_uint(s);
    u = (u & 0x80000000u) ? ~u : (u | 0x80000000u);
    return (((unsigned long long)u) << 32) | (unsigned)k;
}

// packed f32x2 FMA (Blackwell): d = a*b + d elementwise on two fp32 lanes
__device__ __forceinline__ void fma2(unsigned long long& d,
                                     unsigned long long a,
                                     unsigned long long b) {
    asm("fma.rn.f32x2 %0, %1, %2, %0;" : "+l"(d) : "l"(a), "l"(b));
}
__device__ __forceinline__ unsigned long long splat2(float v) {
    unsigned long long r;
    unsigned u = __float_as_uint(v);
    asm("mov.b64 %0, {%1, %1};" : "=l"(r) : "r"(u));
    return r;
}

// ---------------- kernel 1: init outputs + scratch ---------------------------
__global__ void init_kernel(const float* __restrict__ usage,
                            const float* __restrict__ ces,
                            float* __restrict__ out_usage,
                            float* __restrict__ out_ces, int N) {
    int i = blockIdx.x * blockDim.x + threadIdx.x;
    const float om = 1.0f - 0.01f;                 // matches (1.0 - s) in fp32
    if (i < KCB * CCH) out_ces[i] = ces[i] * om;
    if (i < KCB)       out_usage[i] = usage[i] * om;
    if (i < N)         g_best[i] = 0xFFFFFFFFFFFFFFFFull;
    if (i == 0)        g_loss_sum = 0.0f;
}

// ---------------- kernel 2: codebook = ces / clip(usage) + row norms --------
__global__ void prep_kernel(const float* __restrict__ usage,
                            const float* __restrict__ ces) {
    int k = blockIdx.x;
    int t = threadIdx.x;                           // 64 threads, 4 floats each
    float u = fmaxf(usage[k], 1e-5f);
    float4 v = *reinterpret_cast<const float4*>(ces + (size_t)k * CCH + t * 4);
    float4 cb;
    cb.x = v.x / u; cb.y = v.y / u; cb.z = v.z / u; cb.w = v.w / u;
    *reinterpret_cast<float4*>(g_codebook + (size_t)k * CCH + t * 4) = cb;
    float s = cb.x * cb.x + cb.y * cb.y + cb.z * cb.z + cb.w * cb.w;
#pragma unroll
    for (int off = 16; off > 0; off >>= 1)
        s += __shfl_xor_sync(0xffffffffu, s, off);
    __shared__ float ws[2];
    if ((t & 31) == 0) ws[t >> 5] = s;
    __syncthreads();
    if (t == 0) g_cbsq[k] = ws[0] + ws[1];
}

// ---------------- kernel 3: fused fp32 GEMM + argmin ------------------------
// CTA tile: 128 tokens x 128 codes, full-C accumulation in fp32 via fma.f32x2.
// grid = (N/128, K/2048); each CTA covers 16 consecutive 128-code tiles.
__global__ __launch_bounds__(256, 2)
void gemm_argmin_kernel(const float* __restrict__ X, int N) {
    __shared__ __align__(16) float sh[2 * 32 * 132];
    float* sx = sh;                 // [32 c][132] tokens (padded)
    float* sc = sh + 32 * 132;      // [32 c][132] codes  (padded)

    const int tid   = threadIdx.x;
    const int kg    = tid >> 4;     // 0..15 (code group)
    const int ng    = tid & 15;     // 0..15 (token group)
    const int k_sub = kg * 8;
    const int n_sub = ng * 8;
    const int n0    = blockIdx.x * 128;
    const int kt0   = blockIdx.y * 16;

    unsigned long long best[8];
#pragma unroll
    for (int j = 0; j < 8; j++) best[j] = 0xFFFFFFFFFFFFFFFFull;

    for (int kt = 0; kt < 16; kt++) {
        const int k0 = (kt0 + kt) * 128;

        unsigned long long acc[32];     // 8 codes x 4 token-pairs (f32x2)
#pragma unroll
        for (int i = 0; i < 32; i++) acc[i] = 0ull;

        for (int c0 = 0; c0 < CCH; c0 += 32) {
            __syncthreads();   // previous users of sx/sc are done
            // load + transpose 128x32 tiles of X and codebook into smem
#pragma unroll
            for (int i = 0; i < 4; i++) {
                int e = i * 256 + tid;
                int q = e >> 7;        // 0..7 (float4 column group)
                int r = e & 127;       // row within tile
                float4 xv = *reinterpret_cast<const float4*>(
                    X + (size_t)(n0 + r) * CCH + c0 + q * 4);
                sx[(q * 4 + 0) * 132 + r] = xv.x;
                sx[(q * 4 + 1) * 132 + r] = xv.y;
                sx[(q * 4 + 2) * 132 + r] = xv.z;
                sx[(q * 4 + 3) * 132 + r] = xv.w;
                float4 cv = *reinterpret_cast<const float4*>(
                    g_codebook + (size_t)(k0 + r) * CCH + c0 + q * 4);
                sc[(q * 4 + 0) * 132 + r] = cv.x;
                sc[(q * 4 + 1) * 132 + r] = cv.y;
                sc[(q * 4 + 2) * 132 + r] = cv.z;
                sc[(q * 4 + 3) * 132 + r] = cv.w;
            }
            __syncthreads();

#pragma unroll 4
            for (int c = 0; c < 32; c++) {
                const float* xr = sx + c * 132 + n_sub;
                ulonglong2 p0 = *reinterpret_cast<const ulonglong2*>(xr);
                ulonglong2 p1 = *reinterpret_cast<const ulonglong2*>(xr + 4);
                const float* cr = sc + c * 132 + k_sub;
                float4 a0 = *reinterpret_cast<const float4*>(cr);
                float4 a1 = *reinterpret_cast<const float4*>(cr + 4);
                float av[8] = {a0.x, a0.y, a0.z, a0.w, a1.x, a1.y, a1.z, a1.w};
#pragma unroll
                for (int ki = 0; ki < 8; ki++) {
                    unsigned long long s = splat2(av[ki]);
                    fma2(acc[ki * 4 + 0], s, p0.x);
                    fma2(acc[ki * 4 + 1], s, p0.y);
                    fma2(acc[ki * 4 + 2], s, p1.x);
                    fma2(acc[ki * 4 + 3], s, p1.y);
                }
            }
        }

        // per-k-tile epilogue: score = cb_sq - 2*dot, update running best
#pragma unroll
        for (int ki = 0; ki < 8; ki++) {
            const int kglob = k0 + k_sub + ki;
            const float cq = g_cbsq[kglob];
#pragma unroll
            for (int nj = 0; nj < 4; nj++) {
                unsigned long long p = acc[ki * 4 + nj];
                float d0 = __uint_as_float((unsigned)(p & 0xffffffffull));
                float d1 = __uint_as_float((unsigned)(p >> 32));
                unsigned long long e0 = pack_key(fmaf(-2.0f, d0, cq), kglob);
                unsigned long long e1 = pack_key(fmaf(-2.0f, d1, cq), kglob);
                if (e0 < best[2 * nj])     best[2 * nj] = e0;
                if (e1 < best[2 * nj + 1]) best[2 * nj + 1] = e1;
            }
        }
    }

    // CTA reduction across the 16 code-groups, then global atomicMin
    __syncthreads();
    unsigned long long* red = reinterpret_cast<unsigned long long*>(sh);
#pragma unroll
    for (int j = 0; j < 8; j++) red[kg * 128 + n_sub + j] = best[j];
    __syncthreads();
    if (tid < 128) {
        unsigned long long m = red[tid];
#pragma unroll
        for (int g = 1; g < 16; g++) {
            unsigned long long v = red[g * 128 + tid];
            if (v < m) m = v;
        }
        atomicMin(&g_best[n0 + tid], m);
    }
}

// ---------------- kernel 4: gather/STE/loss/EMA scatter ---------------------
__global__ void finish_kernel(const float* __restrict__ X,
                              float* __restrict__ out_codes,
                              float* __restrict__ out_q,
                              float* __restrict__ out_usage,
                              float* __restrict__ out_ces, int N) {
    const int warp = threadIdx.x >> 5;
    const int lane = threadIdx.x & 31;
    const int n = blockIdx.x * 8 + warp;
    if (n >= N) return;
    const int k = (int)(unsigned)(g_best[n] & 0xffffffffull);
    const float* xr = X + (size_t)n * CCH;
    const float* qr = g_codebook + (size_t)k * CCH;
    float ls = 0.0f;
#pragma unroll
    for (int t = 0; t < 2; t++) {
        const int c = lane * 8 + t * 4;
        float4 xv = *reinterpret_cast<const float4*>(xr + c);
        float4 qv = *reinterpret_cast<const float4*>(qr + c);
        float4 ev;
        ev.x = xv.x + (qv.x - xv.x);
        ev.y = xv.y + (qv.y - xv.y);
        ev.z = xv.z + (qv.z - xv.z);
        ev.w = xv.w + (qv.w - xv.w);
        *reinterpret_cast<float4*>(out_q + (size_t)n * CCH + c) = ev;
        float dx = ev.x - xv.x, dy = ev.y - xv.y, dz = ev.z - xv.z, dw = ev.w - xv.w;
        ls += dx * dx + dy * dy + dz * dz + dw * dw;
        // EMA embedding-sum scatter: out_ces already holds 0.99*ces
        atomicAdd(&out_ces[(size_t)k * CCH + c + 0], 0.01f * xv.x);
        atomicAdd(&out_ces[(size_t)k * CCH + c + 1], 0.01f * xv.y);
        atomicAdd(&out_ces[(size_t)k * CCH + c + 2], 0.01f * xv.z);
        atomicAdd(&out_ces[(size_t)k * CCH + c + 3], 0.01f * xv.w);
    }
#pragma unroll
    for (int off = 16; off > 0; off >>= 1)
        ls += __shfl_xor_sync(0xffffffffu, ls, off);
    if (lane == 0) {
        out_codes[n] = (float)k;
        atomicAdd(&out_usage[k], 0.01f);
        atomicAdd(&g_loss_sum, ls);
    }
}

// ---------------- kernel 5: finalize loss -----------------------------------
__global__ void write_loss_kernel(float* __restrict__ dst, float scale) {
    dst[0] = g_loss_sum * scale;
}

// ---------------- launcher ---------------------------------------------------
extern "C" void kernel_launch(void* const* d_in, const int* in_sizes, int n_in,
                              void* d_out, int out_size) {
    const float* X     = (const float*)d_in[0];  // embeddings [N, 256]
    const float* usage = (const float*)d_in[1];  // [8192]
    const float* ces   = (const float*)d_in[2];  // [8192, 256]
    const int N = in_sizes[0] / CCH;             // 32768

    // output layout: codes[N], embeddings_q[N*C], loss[1], usage[K], ces[K*C]
    float* out        = (float*)d_out;
    float* out_codes  = out;
    float* out_q      = out + N;
    float* out_loss   = out + N + (size_t)N * CCH;
    float* out_usage  = out_loss + 1;
    float* out_ces    = out_usage + KCB;

    init_kernel<<<(KCB * CCH + 255) / 256, 256>>>(usage, ces, out_usage, out_ces, N);
    prep_kernel<<<KCB, 64>>>(usage, ces);

    dim3 grid(N / 128, KCB / (128 * 16));        // (256, 4)
    gemm_argmin_kernel<<<grid, 256>>>(X, N);

    finish_kernel<<<(N + 7) / 8, 256>>>(X, out_codes, out_q, out_usage, out_ces, N);

    // N*C = 2^23, so 1/(N*C) is an exact power of two -> multiply == divide
    write_loss_kernel<<<1, 1>>>(out_loss, 1.0f / ((float)N * (float)CCH));
}